// round 14
// baseline (speedup 1.0000x reference)
#include <cuda_runtime.h>
#include <cuda_bf16.h>
#include <cstdint>

typedef unsigned long long ull;

#define D_MODEL   1024
#define D_STATE   128
#define D_INNER   2048
#define NHEADS    32
#define HEADDIM   64
#define CONV_DIM  2304
#define D_IN_PROJ 4384
#define SEQLEN    2048
#define BATCH     2
#define BL        (BATCH * SEQLEN)   // 4096

#define NCHUNK    16
#define CHLEN     128                // SEQLEN / NCHUNK
#define NSLOT     6                  // scan staging ring depth

// ---------------- device scratch ----------------
__device__ float g_zx[(size_t)BL * D_IN_PROJ];
__device__ float g_xconv[(size_t)BL * CONV_DIM];
__device__ float g_dtp[(size_t)BL * NHEADS];
__device__ float g_dA[(size_t)BL * NHEADS];
__device__ float g_y[(size_t)BL * D_INNER];
__device__ float g_cd[(size_t)BATCH * NHEADS * SEQLEN];
__device__ float g_Sloc[(size_t)BATCH * NHEADS * NCHUNK * 64 * 128];
__device__ __nv_bfloat16 g_ssh[(size_t)BATCH * NHEADS * NCHUNK * 64 * 128];
__device__ __nv_bfloat16 g_ssl[(size_t)BATCH * NHEADS * NCHUNK * 64 * 128];
__device__ __nv_bfloat16 g_cbh[(size_t)BL * 128];
__device__ __nv_bfloat16 g_cbl[(size_t)BL * 128];
__device__ __nv_bfloat16 g_xhb[(size_t)BL * D_MODEL];
__device__ __nv_bfloat16 g_xlb[(size_t)BL * D_MODEL];
__device__ __nv_bfloat16 g_w1h[(size_t)D_IN_PROJ * D_MODEL];
__device__ __nv_bfloat16 g_w1l[(size_t)D_IN_PROJ * D_MODEL];
__device__ __nv_bfloat16 g_w2h[(size_t)D_MODEL * D_INNER];
__device__ __nv_bfloat16 g_w2l[(size_t)D_MODEL * D_INNER];
__device__ __nv_bfloat16 g_nh[(size_t)BL * D_INNER];
__device__ __nv_bfloat16 g_nl[(size_t)BL * D_INNER];

// ---------------- PTX helpers ----------------
__device__ __forceinline__ uint32_t smem_u32(const void* p) {
    return (uint32_t)__cvta_generic_to_shared(p);
}
__device__ __forceinline__ void cp_async16(uint32_t dst, const void* src, int nbytes) {
    asm volatile("cp.async.cg.shared.global [%0], [%1], 16, %2;" :: "r"(dst), "l"(src), "r"(nbytes) : "memory");
}
__device__ __forceinline__ void cp_async4(uint32_t dst, const void* src) {
    asm volatile("cp.async.ca.shared.global [%0], [%1], 4;" :: "r"(dst), "l"(src) : "memory");
}
__device__ __forceinline__ void cp_commit() { asm volatile("cp.async.commit_group;" ::: "memory"); }
template<int N> __device__ __forceinline__ void cp_wait() { asm volatile("cp.async.wait_group %0;" :: "n"(N) : "memory"); }

__device__ __forceinline__ void ldsm4(uint32_t* r, uint32_t addr) {
    asm volatile("ldmatrix.sync.aligned.m8n8.x4.shared.b16 {%0,%1,%2,%3}, [%4];"
        : "=r"(r[0]), "=r"(r[1]), "=r"(r[2]), "=r"(r[3]) : "r"(addr));
}
__device__ __forceinline__ void mma16816(float* d, const uint32_t* a, const uint32_t* b) {
    asm volatile("mma.sync.aligned.m16n8k16.row.col.f32.bf16.bf16.f32 "
        "{%0,%1,%2,%3}, {%4,%5,%6,%7}, {%8,%9}, {%0,%1,%2,%3};"
        : "+f"(d[0]), "+f"(d[1]), "+f"(d[2]), "+f"(d[3])
        : "r"(a[0]), "r"(a[1]), "r"(a[2]), "r"(a[3]), "r"(b[0]), "r"(b[1]));
}

__device__ __forceinline__ ull f2fma(ull a, ull b, ull c) { ull d; asm("fma.rn.f32x2 %0, %1, %2, %3;" : "=l"(d) : "l"(a), "l"(b), "l"(c)); return d; }
__device__ __forceinline__ ull f2mul(ull a, ull b) { ull d; asm("mul.rn.f32x2 %0, %1, %2;" : "=l"(d) : "l"(a), "l"(b)); return d; }
__device__ __forceinline__ ull f2pack(float x) { ull d; asm("mov.b64 %0, {%1, %2};" : "=l"(d) : "f"(x), "f"(x)); return d; }
__device__ __forceinline__ float f2sum(ull a) { float lo, hi; asm("mov.b64 {%0, %1}, %2;" : "=f"(lo), "=f"(hi) : "l"(a)); return lo + hi; }

__device__ __forceinline__ void splitull(ull v, uint32_t& hh, uint32_t& ll) {
    float a, b;
    asm("mov.b64 {%0, %1}, %2;" : "=f"(a), "=f"(b) : "l"(v));
    __nv_bfloat16 ha = __float2bfloat16_rn(a), hb = __float2bfloat16_rn(b);
    __nv_bfloat16 la = __float2bfloat16_rn(a - __bfloat162float(ha));
    __nv_bfloat16 lb = __float2bfloat16_rn(b - __bfloat162float(hb));
    uint16_t uha = *(uint16_t*)&ha, uhb = *(uint16_t*)&hb;
    uint16_t ula = *(uint16_t*)&la, ulb = *(uint16_t*)&lb;
    hh = (uint32_t)uha | ((uint32_t)uhb << 16);
    ll = (uint32_t)ula | ((uint32_t)ulb << 16);
}

// =====================================================================
// bf16 3-term-split GEMM (R11 config): BM=128 BN=128 BK=32, 2-stage,
// 2 CTAs/SM, 8 warps 4x2, warp tile 32x64.
// =====================================================================
#define ROW_B   80
#define TILE_B  (128 * ROW_B)
#define STAGE_B (4 * TILE_B)
#define GSMEM   (2 * STAGE_B)

__global__ __launch_bounds__(256, 2) void gemm_mma(
    const __nv_bfloat16* __restrict__ Ah, const __nv_bfloat16* __restrict__ Al,
    const __nv_bfloat16* __restrict__ Bh, const __nv_bfloat16* __restrict__ Bl,
    float* __restrict__ C, const float* __restrict__ resid,
    int M, int N, int K)
{
    extern __shared__ char sm[];
    const uint32_t smb = smem_u32(sm);
    const int tid  = threadIdx.x;
    const int wid  = tid >> 5;
    const int lane = tid & 31;
    const int bm = blockIdx.y * 128;
    const int bn = blockIdx.x * 128;
    const int wm = (wid & 3) * 32;
    const int wn = (wid >> 2) * 64;

    const __nv_bfloat16* srcs[4] = {Ah, Al, Bh, Bl};

    auto stage = [&](int it, int buf) {
        const int k0 = it * 32;
#pragma unroll
        for (int i = 0; i < 8; i++) {
            int f = tid + i * 256;
            int tsel = f >> 9;
            int c = f & 511;
            int r = c >> 2;
            int cc = c & 3;
            uint32_t dst = smb + buf * STAGE_B + tsel * TILE_B + r * ROW_B + cc * 16;
            int row = (tsel < 2) ? (bm + r) : (bn + r);
            int nb = 16;
            if (tsel >= 2 && row >= N) { row = bn; nb = 0; }
            cp_async16(dst, srcs[tsel] + (size_t)row * K + k0 + cc * 8, nb);
        }
    };

    const int jj = lane >> 3;
    const int lr = lane & 7;
    const int aRow = (jj & 1) * 8 + lr;
    const int aColB = (jj >> 1) * 16;
    const int bRow = (jj >> 1) * 8 + lr;
    const int bColB = (jj & 1) * 16;

    float acc[2][8][4];
#pragma unroll
    for (int mt = 0; mt < 2; mt++)
#pragma unroll
        for (int j = 0; j < 8; j++)
#pragma unroll
            for (int e = 0; e < 4; e++) acc[mt][j][e] = 0.f;

    const int NIT = K >> 5;
    stage(0, 0);
    cp_commit();

    for (int it = 0; it < NIT; it++) {
        const int buf = it & 1;
        if (it + 1 < NIT) { stage(it + 1, buf ^ 1); cp_commit(); cp_wait<1>(); }
        else              { cp_wait<0>(); }
        __syncthreads();

        const uint32_t ab  = smb + buf * STAGE_B;
        const uint32_t alb = ab + TILE_B;
        const uint32_t bhb = ab + 2 * TILE_B;
        const uint32_t blb = ab + 3 * TILE_B;

#pragma unroll
        for (int ks = 0; ks < 2; ks++) {
            uint32_t ah[2][4], alf[2][4], bh[4][4], blf[4][4];
#pragma unroll
            for (int mt = 0; mt < 2; mt++) {
                uint32_t off = (uint32_t)((wm + mt * 16 + aRow) * ROW_B + ks * 32 + aColB);
                ldsm4(ah[mt],  ab  + off);
                ldsm4(alf[mt], alb + off);
            }
#pragma unroll
            for (int pn = 0; pn < 4; pn++) {
                uint32_t off = (uint32_t)((wn + pn * 16 + bRow) * ROW_B + ks * 32 + bColB);
                ldsm4(bh[pn],  bhb + off);
                ldsm4(blf[pn], blb + off);
            }
#pragma unroll
            for (int mt = 0; mt < 2; mt++)
#pragma unroll
                for (int j = 0; j < 8; j++) {
                    const uint32_t* bf  = bh[j >> 1] + (j & 1) * 2;
                    const uint32_t* bl2 = blf[j >> 1] + (j & 1) * 2;
                    mma16816(acc[mt][j], ah[mt],  bf);
                    mma16816(acc[mt][j], alf[mt], bf);
                    mma16816(acc[mt][j], ah[mt],  bl2);
                }
        }
        __syncthreads();
    }

    const int r0 = bm + wm + (lane >> 2);
#pragma unroll
    for (int mt = 0; mt < 2; mt++) {
#pragma unroll
        for (int j = 0; j < 8; j++) {
            int col = bn + wn + (j >> 1) * 16 + (j & 1) * 8 + (lane & 3) * 2;
            if (col < N) {
                int r1 = r0 + mt * 16;
                int r2 = r1 + 8;
                float2 v1 = make_float2(acc[mt][j][0], acc[mt][j][1]);
                float2 v2 = make_float2(acc[mt][j][2], acc[mt][j][3]);
                if (resid) {
                    float2 q1 = *(const float2*)(resid + (size_t)r1 * N + col);
                    float2 q2 = *(const float2*)(resid + (size_t)r2 * N + col);
                    v1.x += q1.x; v1.y += q1.y; v2.x += q2.x; v2.y += q2.y;
                }
                *(float2*)(C + (size_t)r1 * N + col) = v1;
                *(float2*)(C + (size_t)r2 * N + col) = v2;
            }
        }
    }
}

// =====================================================================
// fused operand splits: x (4.19M), w1 (4.49M), w2 (2.10M) in one launch
// =====================================================================
#define SPLIT_N0 (BL * D_MODEL)
#define SPLIT_N1 (D_IN_PROJ * D_MODEL)
#define SPLIT_N2 (D_MODEL * D_INNER)

__global__ __launch_bounds__(256) void split_all_kernel(
    const float* __restrict__ x, const float* __restrict__ w1,
    const float* __restrict__ w2)
{
    int i = blockIdx.x * 256 + threadIdx.x;
    const float* src;
    __nv_bfloat16 *hi, *lo;
    if (i < SPLIT_N0) { src = x; hi = g_xhb; lo = g_xlb; }
    else if (i < SPLIT_N0 + SPLIT_N1) { i -= SPLIT_N0; src = w1; hi = g_w1h; lo = g_w1l; }
    else if (i < SPLIT_N0 + SPLIT_N1 + SPLIT_N2) { i -= SPLIT_N0 + SPLIT_N1; src = w2; hi = g_w2h; lo = g_w2l; }
    else return;
    float v = src[i];
    __nv_bfloat16 h = __float2bfloat16_rn(v);
    hi[i] = h;
    lo[i] = __float2bfloat16_rn(v - __bfloat162float(h));
}

// conv + silu + C-split; block col 9 additionally runs dt preprocessing
__global__ __launch_bounds__(256) void conv_silu_kernel(
    const float* __restrict__ cw, const float* __restrict__ cb,
    const float* __restrict__ dt_bias, const float* __restrict__ A_log)
{
    int row = blockIdx.y;
    if (blockIdx.x == 9) {
        if (threadIdx.x < 32) {
            int hh = threadIdx.x;
            float v = g_zx[(size_t)row * D_IN_PROJ + (D_INNER + CONV_DIM) + hh] + dt_bias[hh];
            float sp = (v > 20.f) ? v : log1pf(expf(v));
            g_dtp[row * NHEADS + hh] = sp;
            g_dA[row * NHEADS + hh] = expf(-expf(A_log[hh]) * sp);
        }
        return;
    }
    int c = blockIdx.x * 256 + threadIdx.x;
    int t = row & (SEQLEN - 1);
    float4 w = *(const float4*)(cw + c * 4);
    const float* wv = (const float*)&w;
    const float* col = g_zx + (size_t)row * D_IN_PROJ + D_INNER + c;
    float s = 0.f;
#pragma unroll
    for (int j = 0; j < 4; j++) {
        int tt = t - 3 + j;
        if (tt >= 0) s = fmaf(wv[j], col[(j - 3) * D_IN_PROJ], s);
    }
    s += cb[c];
    float val = s / (1.f + expf(-s));
    g_xconv[(size_t)row * CONV_DIM + c] = val;
    if (c >= D_INNER + D_STATE) {
        int n = c - (D_INNER + D_STATE);
        __nv_bfloat16 h = __float2bfloat16_rn(val);
        g_cbh[(size_t)row * 128 + n] = h;
        g_cbl[(size_t)row * 128 + n] = __float2bfloat16_rn(val - __bfloat162float(h));
    }
}

// =====================================================================
// Phase 1: local chunk scan. 1024 blocks, 128 thr, 4 blocks/SM cap,
// 6-slot staging ring (prefetch distance 5 iterations).
// =====================================================================
__global__ __launch_bounds__(128, 4) void scan_local_kernel(const float* __restrict__ Dv)
{
    const int bx = blockIdx.x;
    const int chunk = bx & (NCHUNK - 1);
    const int h  = (bx >> 4) & 31;
    const int bi = bx >> 9;
    const int tid = threadIdx.x;
    const int pg = tid >> 3;
    const int ng = tid & 7;

    __shared__ __align__(16) float sB[NSLOT][4][128];
    __shared__ __align__(16) float sC[NSLOT][4][128];
    __shared__ __align__(16) float sxs[NSLOT][4][64];
    __shared__ __align__(16) float ssc[NSLOT][4][2];

    int fof[4];
#pragma unroll
    for (int j = 0; j < 4; j++) fof[j] = ng * 16 + ((j + (ng >> 1)) & 3) * 4;

    ull S[4][8];
#pragma unroll
    for (int p = 0; p < 4; p++)
#pragma unroll
        for (int j = 0; j < 8; j++) S[p][j] = 0ULL;

    const float Dh = Dv[h];
    const float* xcb = g_xconv + (size_t)bi * SEQLEN * CONV_DIM;
    const float* dAb = g_dA  + (size_t)bi * SEQLEN * NHEADS + h;
    const float* dtb = g_dtp + (size_t)bi * SEQLEN * NHEADS + h;
    const int t0 = chunk * CHLEN;

    auto stage4 = [&](int t, int pi) {
#pragma unroll
        for (int k = 0; k < 3; k++) {
            int c = tid + k * 128;
            if (c >= 328) break;
            int s = c / 82;
            int cc = c - s * 82;
            const float* rowp = xcb + (size_t)(t + s) * CONV_DIM;
            if (cc < 32)       cp_async16(smem_u32(&sB[pi][s][cc * 4]),  rowp + D_INNER + cc * 4, 16);
            else if (cc < 64)  cp_async16(smem_u32(&sC[pi][s][(cc - 32) * 4]), rowp + D_INNER + D_STATE + (cc - 32) * 4, 16);
            else if (cc < 80)  cp_async16(smem_u32(&sxs[pi][s][(cc - 64) * 4]), rowp + h * 64 + (cc - 64) * 4, 16);
            else if (cc == 80) cp_async4(smem_u32(&ssc[pi][s][0]), dAb + (size_t)(t + s) * NHEADS);
            else               cp_async4(smem_u32(&ssc[pi][s][1]), dtb + (size_t)(t + s) * NHEADS);
        }
    };

#pragma unroll
    for (int sl = 0; sl < NSLOT; sl++) { stage4(t0 + sl * 4, sl); cp_commit(); }

    float* yout = g_y + (size_t)bi * SEQLEN * D_INNER + h * 64 + pg * 4;
    float* cdout = g_cd + ((size_t)bi * NHEADS + h) * SEQLEN;
    float cdv = 1.f;

    const int NITER = CHLEN / 4;
    int pi = 0;
    for (int it = 0; it < NITER; it++) {
        const int t = t0 + it * 4;
        cp_wait<NSLOT - 1>();
        __syncthreads();

        float2 sc[4];
        float4 xs[4];
#pragma unroll
        for (int s = 0; s < 4; s++) {
            sc[s] = *(const float2*)&ssc[pi][s][0];
            xs[s] = *(const float4*)&sxs[pi][s][pg * 4];
        }

        float yv[4][4];
#pragma unroll
        for (int s = 0; s < 4; s++) {
            float4 B4[4], C4[4];
#pragma unroll
            for (int j = 0; j < 4; j++) {
                B4[j] = *(const float4*)(&sB[pi][s][0] + fof[j]);
                C4[j] = *(const float4*)(&sC[pi][s][0] + fof[j]);
            }
            const ull dA2 = f2pack(sc[s].x);
            const float dtv = sc[s].y;
            cdv *= sc[s].x;
            if (tid == 0) cdout[t + s] = cdv;
#pragma unroll
            for (int p = 0; p < 4; p++) {
                const float xv = ((const float*)&xs[s])[p];
                const ull xdt2 = f2pack(xv * dtv);
                ull a0 = 0ULL, a1 = 0ULL;
#pragma unroll
                for (int j = 0; j < 4; j++) {
                    const ull b0 = ((const ull*)&B4[j])[0];
                    const ull b1 = ((const ull*)&B4[j])[1];
                    const ull c0 = ((const ull*)&C4[j])[0];
                    const ull c1 = ((const ull*)&C4[j])[1];
                    S[p][2 * j]     = f2fma(dA2, S[p][2 * j],     f2mul(xdt2, b0));
                    S[p][2 * j + 1] = f2fma(dA2, S[p][2 * j + 1], f2mul(xdt2, b1));
                    if (j == 0) { a0 = f2mul(S[p][0], c0); a1 = f2mul(S[p][1], c1); }
                    else        { a0 = f2fma(S[p][2 * j], c0, a0); a1 = f2fma(S[p][2 * j + 1], c1, a1); }
                }
                yv[p][s] = f2sum(a0) + f2sum(a1);
            }
        }

#pragma unroll
        for (int o = 1; o < 8; o <<= 1) {
#pragma unroll
            for (int p = 0; p < 4; p++)
#pragma unroll
                for (int s = 0; s < 4; s++)
                    yv[p][s] += __shfl_xor_sync(0xffffffffu, yv[p][s], o);
        }
        if (ng == 0) {
#pragma unroll
            for (int s = 0; s < 4; s++) {
                float4 v;
                v.x = fmaf(Dh, ((const float*)&xs[s])[0], yv[0][s]);
                v.y = fmaf(Dh, ((const float*)&xs[s])[1], yv[1][s]);
                v.z = fmaf(Dh, ((const float*)&xs[s])[2], yv[2][s]);
                v.w = fmaf(Dh, ((const float*)&xs[s])[3], yv[3][s]);
                *(float4*)(yout + (size_t)(t + s) * D_INNER) = v;
            }
        }
        __syncthreads();
        if (it + NSLOT < NITER) stage4(t + NSLOT * 4, pi);
        cp_commit();
        pi = (pi + 1 == NSLOT) ? 0 : pi + 1;
    }

    float* slb = g_Sloc + (((size_t)(bi * NHEADS + h) * NCHUNK + chunk) * 64 + pg * 4) * 128 + ng * 16;
#pragma unroll
    for (int p = 0; p < 4; p++)
#pragma unroll
        for (int j = 0; j < 4; j++) {
            int m = (j + (ng >> 1)) & 3;
            *(ull*)(slb + p * 128 + m * 4)     = S[p][2 * j];
            *(ull*)(slb + p * 128 + m * 4 + 2) = S[p][2 * j + 1];
        }
}

// =====================================================================
// Phase 2: sequential chunk-state combine (128 blocks = (b,h) x n-half)
// =====================================================================
__global__ __launch_bounds__(256) void combine_kernel()
{
    const int bh = blockIdx.x >> 1;
    const int half = blockIdx.x & 1;
    const int tid = threadIdx.x;
    const int base = half * 2048;
    const ull* sl = (const ull*)(g_Sloc + (size_t)bh * NCHUNK * 8192);
    uint32_t* sh  = (uint32_t*)g_ssh + (size_t)bh * NCHUNK * 4096;
    uint32_t* slo = (uint32_t*)g_ssl + (size_t)bh * NCHUNK * 4096;
    const float* cdp = g_cd + (size_t)bh * SEQLEN;

    ull s[8];
#pragma unroll
    for (int k = 0; k < 8; k++) s[k] = 0ULL;

    for (int j = 0; j < NCHUNK; j++) {
#pragma unroll
        for (int k = 0; k < 8; k++) {
            uint32_t hh, ll;
            splitull(s[k], hh, ll);
            sh [(size_t)j * 4096 + base + tid + k * 256] = hh;
            slo[(size_t)j * 4096 + base + tid + k * 256] = ll;
        }
        const ull cd2 = f2pack(cdp[j * CHLEN + CHLEN - 1]);
#pragma unroll
        for (int k = 0; k < 8; k++)
            s[k] = f2fma(cd2, s[k], sl[(size_t)j * 4096 + base + tid + k * 256]);
    }
}

// =====================================================================
// Phase 3 (tensorized correction, unchanged)
// =====================================================================
#define CR_CH 0
#define CR_CL 34816
#define CR_SH 69632
#define CR_SL 87040
#define CR_CD 104448
#define CR_SMEM 104960

__global__ __launch_bounds__(128) void correct_mma_kernel()
{
    extern __shared__ char sm[];
    const uint32_t smb = smem_u32(sm);
    const int bx = blockIdx.x;
    const int chunk = bx % (NCHUNK - 1) + 1;
    const int h  = (bx / (NCHUNK - 1)) % NHEADS;
    const int bi = bx / ((NCHUNK - 1) * NHEADS);
    const int tid = threadIdx.x;
    const int wid = tid >> 5;
    const int lane = tid & 31;
    const int t0 = chunk * CHLEN;
    const size_t bh = (size_t)bi * NHEADS + h;

    const __nv_bfloat16* Cgh = g_cbh + ((size_t)bi * SEQLEN + t0) * 128;
    const __nv_bfloat16* Cgl = g_cbl + ((size_t)bi * SEQLEN + t0) * 128;
    const __nv_bfloat16* Sgh = g_ssh + (bh * NCHUNK + chunk) * 8192;
    const __nv_bfloat16* Sgl = g_ssl + (bh * NCHUNK + chunk) * 8192;

#pragma unroll
    for (int i = 0; i < 16; i++) {
        int id = tid + i * 128;
        int row = id >> 4, cc = id & 15;
        cp_async16(smb + CR_CH + row * 272 + cc * 16, Cgh + row * 128 + cc * 8, 16);
        cp_async16(smb + CR_CL + row * 272 + cc * 16, Cgl + row * 128 + cc * 8, 16);
    }
#pragma unroll
    for (int i = 0; i < 8; i++) {
        int id = tid + i * 128;
        int row = id >> 4, cc = id & 15;
        cp_async16(smb + CR_SH + row * 272 + cc * 16, Sgh + row * 128 + cc * 8, 16);
        cp_async16(smb + CR_SL + row * 272 + cc * 16, Sgl + row * 128 + cc * 8, 16);
    }
    cp_async4(smb + CR_CD + tid * 4, g_cd + bh * SEQLEN + t0 + tid);
    cp_commit();
    cp_wait<0>();
    __syncthreads();

    const int jj = lane >> 3;
    const int lr = lane & 7;
    const int aRow = (jj & 1) * 8 + lr;
    const int aColB = (jj >> 1) * 16;
    const int bRow = (jj >> 1) * 8 + lr;
    const int bColB = (jj & 1) * 16;
    const int wm = wid * 32;

    float acc[2][8][4];
#pragma unroll
    for (int mt = 0; mt < 2; mt++)
#pragma unroll
        for (int j = 0; j < 8; j++)
#pragma unroll
            for (int e = 0; e < 4; e++) acc[mt][j][e] = 0.f;

#pragma unroll
    for (int ks = 0; ks < 8; ks++) {
        uint32_t ah[2][4], al[2][4], bh4[4][4], bl4[4][4];
#pragma unroll
        for (int mt = 0; mt < 2; mt++) {
            uint32_t off = (uint32_t)((wm + mt * 16 + aRow) * 272 + ks * 32 + aColB);
            ldsm4(ah[mt], smb + CR_CH + off);
            ldsm4(al[mt], smb + CR_CL + off);
        }
#pragma unroll
        for (int pn = 0; pn < 4; pn++) {
            uint32_t off = (uint32_t)((pn * 16 + bRow) * 272 + ks * 32 + bColB);
            ldsm4(bh4[pn], smb + CR_SH + off);
            ldsm4(bl4[pn], smb + CR_SL + off);
        }
#pragma unroll
        for (int mt = 0; mt < 2; mt++)
#pragma unroll
            for (int j = 0; j < 8; j++) {
                const uint32_t* bf  = bh4[j >> 1] + (j & 1) * 2;
                const uint32_t* bl2 = bl4[j >> 1] + (j & 1) * 2;
                mma16816(acc[mt][j], ah[mt], bf);
                mma16816(acc[mt][j], al[mt], bf);
                mma16816(acc[mt][j], ah[mt], bl2);
            }
    }

    const float* cds = (const float*)(sm + CR_CD);
    float* yb = g_y + ((size_t)bi * SEQLEN + t0) * D_INNER + h * 64;
    const int r0 = wm + (lane >> 2);
#pragma unroll
    for (int mt = 0; mt < 2; mt++) {
#pragma unroll
        for (int j = 0; j < 8; j++) {
            int col = (j >> 1) * 16 + (j & 1) * 8 + (lane & 3) * 2;
            int r1 = r0 + mt * 16;
            int r2 = r1 + 8;
            float2 y1 = *(float2*)(yb + (size_t)r1 * D_INNER + col);
            float2 y2 = *(float2*)(yb + (size_t)r2 * D_INNER + col);
            float c1 = cds[r1], c2 = cds[r2];
            y1.x = fmaf(c1, acc[mt][j][0], y1.x);
            y1.y = fmaf(c1, acc[mt][j][1], y1.y);
            y2.x = fmaf(c2, acc[mt][j][2], y2.x);
            y2.y = fmaf(c2, acc[mt][j][3], y2.y);
            *(float2*)(yb + (size_t)r1 * D_INNER + col) = y1;
            *(float2*)(yb + (size_t)r2 * D_INNER + col) = y2;
        }
    }
}

// =====================================================================
__global__ __launch_bounds__(256) void gatenorm_kernel(const float* __restrict__ nw)
{
    int row = blockIdx.x;
    int tid = threadIdx.x;
    const float* yr = g_y + (size_t)row * D_INNER;
    const float* zr = g_zx + (size_t)row * D_IN_PROJ;
    float v[8];
    float ss = 0.f;
#pragma unroll
    for (int i = 0; i < 8; i++) {
        int c = tid + i * 256;
        float z = zr[c];
        float val = yr[c] * (z / (1.f + expf(-z)));
        v[i] = val;
        ss = fmaf(val, val, ss);
    }
#pragma unroll
    for (int o = 16; o; o >>= 1) ss += __shfl_xor_sync(0xffffffffu, ss, o);
    __shared__ float red[8];
    if ((tid & 31) == 0) red[tid >> 5] = ss;
    __syncthreads();
    float tot = red[0] + red[1] + red[2] + red[3] + red[4] + red[5] + red[6] + red[7];
    float scale = rsqrtf(tot * (1.0f / 2048.0f) + 1e-5f);
#pragma unroll
    for (int i = 0; i < 8; i++) {
        int c = tid + i * 256;
        float val = v[i] * scale * nw[c];
        __nv_bfloat16 h = __float2bfloat16_rn(val);
        g_nh[(size_t)row * D_INNER + c] = h;
        g_nl[(size_t)row * D_INNER + c] = __float2bfloat16_rn(val - __bfloat162float(h));
    }
}

// =====================================================================
extern "C" void kernel_launch(void* const* d_in, const int* in_sizes, int n_in,
                              void* d_out, int out_size)
{
    const float* x          = (const float*)d_in[0];
    const float* in_proj_w  = (const float*)d_in[1];
    const float* conv_w     = (const float*)d_in[2];
    const float* conv_b     = (const float*)d_in[3];
    const float* dt_bias    = (const float*)d_in[4];
    const float* A_log      = (const float*)d_in[5];
    const float* Dv         = (const float*)d_in[6];
    const float* norm_w     = (const float*)d_in[7];
    const float* out_proj_w = (const float*)d_in[8];
    float* out = (float*)d_out;

    float *zx;
    __nv_bfloat16 *xh, *xl, *w1h, *w1l, *w2h, *w2l, *nh, *nl;
    cudaGetSymbolAddress((void**)&zx, g_zx);
    cudaGetSymbolAddress((void**)&xh, g_xhb);
    cudaGetSymbolAddress((void**)&xl, g_xlb);
    cudaGetSymbolAddress((void**)&w1h, g_w1h);
    cudaGetSymbolAddress((void**)&w1l, g_w1l);
    cudaGetSymbolAddress((void**)&w2h, g_w2h);
    cudaGetSymbolAddress((void**)&w2l, g_w2l);
    cudaGetSymbolAddress((void**)&nh, g_nh);
    cudaGetSymbolAddress((void**)&nl, g_nl);

    cudaFuncSetAttribute(gemm_mma, cudaFuncAttributeMaxDynamicSharedMemorySize, GSMEM);
    cudaFuncSetAttribute(correct_mma_kernel, cudaFuncAttributeMaxDynamicSharedMemorySize, CR_SMEM);

    const int SPLIT_TOT = SPLIT_N0 + SPLIT_N1 + SPLIT_N2;
    split_all_kernel<<<(SPLIT_TOT + 255) / 256, 256>>>(x, in_proj_w, out_proj_w);

    gemm_mma<<<dim3((D_IN_PROJ + 127) / 128, BL / 128), 256, GSMEM>>>(
        xh, xl, w1h, w1l, zx, nullptr, BL, D_IN_PROJ, D_MODEL);

    conv_silu_kernel<<<dim3(10, BL), 256>>>(conv_w, conv_b, dt_bias, A_log);

    scan_local_kernel<<<BATCH * NHEADS * NCHUNK, 128>>>(Dv);
    combine_kernel<<<BATCH * NHEADS * 2, 256>>>();
    correct_mma_kernel<<<BATCH * NHEADS * (NCHUNK - 1), 128, CR_SMEM>>>();

    gatenorm_kernel<<<BL, 256>>>(norm_w);

    gemm_mma<<<dim3(D_MODEL / 128, BL / 128), 256, GSMEM>>>(
        nh, nl, w2h, w2l, out, x, BL, D_MODEL, D_INNER);
}

// round 15
// speedup vs baseline: 1.0276x; 1.0276x over previous
#include <cuda_runtime.h>
#include <cuda_bf16.h>
#include <cstdint>

typedef unsigned long long ull;

#define D_MODEL   1024
#define D_STATE   128
#define D_INNER   2048
#define NHEADS    32
#define HEADDIM   64
#define CONV_DIM  2304
#define D_IN_PROJ 4384
#define SEQLEN    2048
#define BATCH     2
#define BL        (BATCH * SEQLEN)   // 4096

#define NCHUNK    16
#define CHLEN     128                // SEQLEN / NCHUNK

// ---------------- device scratch ----------------
__device__ float g_zx[(size_t)BL * D_IN_PROJ];
__device__ float g_xconv[(size_t)BL * CONV_DIM];
__device__ float g_dtp[(size_t)BL * NHEADS];
__device__ float g_dA[(size_t)BL * NHEADS];
__device__ float g_y[(size_t)BL * D_INNER];
__device__ float g_cd[(size_t)BATCH * NHEADS * SEQLEN];
__device__ float g_Sloc[(size_t)BATCH * NHEADS * NCHUNK * 64 * 128];
__device__ __nv_bfloat16 g_ssh[(size_t)BATCH * NHEADS * NCHUNK * 64 * 128];
__device__ __nv_bfloat16 g_ssl[(size_t)BATCH * NHEADS * NCHUNK * 64 * 128];
__device__ __nv_bfloat16 g_cbh[(size_t)BL * 128];
__device__ __nv_bfloat16 g_cbl[(size_t)BL * 128];
__device__ __nv_bfloat16 g_xhb[(size_t)BL * D_MODEL];
__device__ __nv_bfloat16 g_xlb[(size_t)BL * D_MODEL];
__device__ __nv_bfloat16 g_w1h[(size_t)D_IN_PROJ * D_MODEL];
__device__ __nv_bfloat16 g_w1l[(size_t)D_IN_PROJ * D_MODEL];
__device__ __nv_bfloat16 g_w2h[(size_t)D_MODEL * D_INNER];
__device__ __nv_bfloat16 g_w2l[(size_t)D_MODEL * D_INNER];
__device__ __nv_bfloat16 g_nh[(size_t)BL * D_INNER];
__device__ __nv_bfloat16 g_nl[(size_t)BL * D_INNER];

// ---------------- PTX helpers ----------------
__device__ __forceinline__ uint32_t smem_u32(const void* p) {
    return (uint32_t)__cvta_generic_to_shared(p);
}
__device__ __forceinline__ void cp_async16(uint32_t dst, const void* src, int nbytes) {
    asm volatile("cp.async.cg.shared.global [%0], [%1], 16, %2;" :: "r"(dst), "l"(src), "r"(nbytes) : "memory");
}
__device__ __forceinline__ void cp_async4(uint32_t dst, const void* src) {
    asm volatile("cp.async.ca.shared.global [%0], [%1], 4;" :: "r"(dst), "l"(src) : "memory");
}
__device__ __forceinline__ void cp_commit() { asm volatile("cp.async.commit_group;" ::: "memory"); }
template<int N> __device__ __forceinline__ void cp_wait() { asm volatile("cp.async.wait_group %0;" :: "n"(N) : "memory"); }

__device__ __forceinline__ void ldsm4(uint32_t* r, uint32_t addr) {
    asm volatile("ldmatrix.sync.aligned.m8n8.x4.shared.b16 {%0,%1,%2,%3}, [%4];"
        : "=r"(r[0]), "=r"(r[1]), "=r"(r[2]), "=r"(r[3]) : "r"(addr));
}
__device__ __forceinline__ void mma16816(float* d, const uint32_t* a, const uint32_t* b) {
    asm volatile("mma.sync.aligned.m16n8k16.row.col.f32.bf16.bf16.f32 "
        "{%0,%1,%2,%3}, {%4,%5,%6,%7}, {%8,%9}, {%0,%1,%2,%3};"
        : "+f"(d[0]), "+f"(d[1]), "+f"(d[2]), "+f"(d[3])
        : "r"(a[0]), "r"(a[1]), "r"(a[2]), "r"(a[3]), "r"(b[0]), "r"(b[1]));
}

__device__ __forceinline__ ull f2fma(ull a, ull b, ull c) { ull d; asm("fma.rn.f32x2 %0, %1, %2, %3;" : "=l"(d) : "l"(a), "l"(b), "l"(c)); return d; }
__device__ __forceinline__ ull f2mul(ull a, ull b) { ull d; asm("mul.rn.f32x2 %0, %1, %2;" : "=l"(d) : "l"(a), "l"(b)); return d; }
__device__ __forceinline__ ull f2pack(float x) { ull d; asm("mov.b64 %0, {%1, %2};" : "=l"(d) : "f"(x), "f"(x)); return d; }
__device__ __forceinline__ float f2sum(ull a) { float lo, hi; asm("mov.b64 {%0, %1}, %2;" : "=f"(lo), "=f"(hi) : "l"(a)); return lo + hi; }

__device__ __forceinline__ void splitull(ull v, uint32_t& hh, uint32_t& ll) {
    float a, b;
    asm("mov.b64 {%0, %1}, %2;" : "=f"(a), "=f"(b) : "l"(v));
    __nv_bfloat16 ha = __float2bfloat16_rn(a), hb = __float2bfloat16_rn(b);
    __nv_bfloat16 la = __float2bfloat16_rn(a - __bfloat162float(ha));
    __nv_bfloat16 lb = __float2bfloat16_rn(b - __bfloat162float(hb));
    uint16_t uha = *(uint16_t*)&ha, uhb = *(uint16_t*)&hb;
    uint16_t ula = *(uint16_t*)&la, ulb = *(uint16_t*)&lb;
    hh = (uint32_t)uha | ((uint32_t)uhb << 16);
    ll = (uint32_t)ula | ((uint32_t)ulb << 16);
}

// =====================================================================
// bf16 3-term-split GEMM (R11 config): BM=128 BN=128 BK=32, 2-stage,
// 2 CTAs/SM, 8 warps 4x2, warp tile 32x64.
// =====================================================================
#define ROW_B   80
#define TILE_B  (128 * ROW_B)
#define STAGE_B (4 * TILE_B)
#define GSMEM   (2 * STAGE_B)

__global__ __launch_bounds__(256, 2) void gemm_mma(
    const __nv_bfloat16* __restrict__ Ah, const __nv_bfloat16* __restrict__ Al,
    const __nv_bfloat16* __restrict__ Bh, const __nv_bfloat16* __restrict__ Bl,
    float* __restrict__ C, const float* __restrict__ resid,
    int M, int N, int K)
{
    extern __shared__ char sm[];
    const uint32_t smb = smem_u32(sm);
    const int tid  = threadIdx.x;
    const int wid  = tid >> 5;
    const int lane = tid & 31;
    const int bm = blockIdx.y * 128;
    const int bn = blockIdx.x * 128;
    const int wm = (wid & 3) * 32;
    const int wn = (wid >> 2) * 64;

    const __nv_bfloat16* srcs[4] = {Ah, Al, Bh, Bl};

    auto stage = [&](int it, int buf) {
        const int k0 = it * 32;
#pragma unroll
        for (int i = 0; i < 8; i++) {
            int f = tid + i * 256;
            int tsel = f >> 9;
            int c = f & 511;
            int r = c >> 2;
            int cc = c & 3;
            uint32_t dst = smb + buf * STAGE_B + tsel * TILE_B + r * ROW_B + cc * 16;
            int row = (tsel < 2) ? (bm + r) : (bn + r);
            int nb = 16;
            if (tsel >= 2 && row >= N) { row = bn; nb = 0; }
            cp_async16(dst, srcs[tsel] + (size_t)row * K + k0 + cc * 8, nb);
        }
    };

    const int jj = lane >> 3;
    const int lr = lane & 7;
    const int aRow = (jj & 1) * 8 + lr;
    const int aColB = (jj >> 1) * 16;
    const int bRow = (jj >> 1) * 8 + lr;
    const int bColB = (jj & 1) * 16;

    float acc[2][8][4];
#pragma unroll
    for (int mt = 0; mt < 2; mt++)
#pragma unroll
        for (int j = 0; j < 8; j++)
#pragma unroll
            for (int e = 0; e < 4; e++) acc[mt][j][e] = 0.f;

    const int NIT = K >> 5;
    stage(0, 0);
    cp_commit();

    for (int it = 0; it < NIT; it++) {
        const int buf = it & 1;
        if (it + 1 < NIT) { stage(it + 1, buf ^ 1); cp_commit(); cp_wait<1>(); }
        else              { cp_wait<0>(); }
        __syncthreads();

        const uint32_t ab  = smb + buf * STAGE_B;
        const uint32_t alb = ab + TILE_B;
        const uint32_t bhb = ab + 2 * TILE_B;
        const uint32_t blb = ab + 3 * TILE_B;

#pragma unroll
        for (int ks = 0; ks < 2; ks++) {
            uint32_t ah[2][4], alf[2][4], bh[4][4], blf[4][4];
#pragma unroll
            for (int mt = 0; mt < 2; mt++) {
                uint32_t off = (uint32_t)((wm + mt * 16 + aRow) * ROW_B + ks * 32 + aColB);
                ldsm4(ah[mt],  ab  + off);
                ldsm4(alf[mt], alb + off);
            }
#pragma unroll
            for (int pn = 0; pn < 4; pn++) {
                uint32_t off = (uint32_t)((wn + pn * 16 + bRow) * ROW_B + ks * 32 + bColB);
                ldsm4(bh[pn],  bhb + off);
                ldsm4(blf[pn], blb + off);
            }
#pragma unroll
            for (int mt = 0; mt < 2; mt++)
#pragma unroll
                for (int j = 0; j < 8; j++) {
                    const uint32_t* bf  = bh[j >> 1] + (j & 1) * 2;
                    const uint32_t* bl2 = blf[j >> 1] + (j & 1) * 2;
                    mma16816(acc[mt][j], ah[mt],  bf);
                    mma16816(acc[mt][j], alf[mt], bf);
                    mma16816(acc[mt][j], ah[mt],  bl2);
                }
        }
        __syncthreads();
    }

    const int r0 = bm + wm + (lane >> 2);
#pragma unroll
    for (int mt = 0; mt < 2; mt++) {
#pragma unroll
        for (int j = 0; j < 8; j++) {
            int col = bn + wn + (j >> 1) * 16 + (j & 1) * 8 + (lane & 3) * 2;
            if (col < N) {
                int r1 = r0 + mt * 16;
                int r2 = r1 + 8;
                float2 v1 = make_float2(acc[mt][j][0], acc[mt][j][1]);
                float2 v2 = make_float2(acc[mt][j][2], acc[mt][j][3]);
                if (resid) {
                    float2 q1 = *(const float2*)(resid + (size_t)r1 * N + col);
                    float2 q2 = *(const float2*)(resid + (size_t)r2 * N + col);
                    v1.x += q1.x; v1.y += q1.y; v2.x += q2.x; v2.y += q2.y;
                }
                *(float2*)(C + (size_t)r1 * N + col) = v1;
                *(float2*)(C + (size_t)r2 * N + col) = v2;
            }
        }
    }
}

// =====================================================================
// fused operand splits: x, w1, w2 in one launch
// =====================================================================
#define SPLIT_N0 (BL * D_MODEL)
#define SPLIT_N1 (D_IN_PROJ * D_MODEL)
#define SPLIT_N2 (D_MODEL * D_INNER)

__global__ __launch_bounds__(256) void split_all_kernel(
    const float* __restrict__ x, const float* __restrict__ w1,
    const float* __restrict__ w2)
{
    int i = blockIdx.x * 256 + threadIdx.x;
    const float* src;
    __nv_bfloat16 *hi, *lo;
    if (i < SPLIT_N0) { src = x; hi = g_xhb; lo = g_xlb; }
    else if (i < SPLIT_N0 + SPLIT_N1) { i -= SPLIT_N0; src = w1; hi = g_w1h; lo = g_w1l; }
    else if (i < SPLIT_N0 + SPLIT_N1 + SPLIT_N2) { i -= SPLIT_N0 + SPLIT_N1; src = w2; hi = g_w2h; lo = g_w2l; }
    else return;
    float v = src[i];
    __nv_bfloat16 h = __float2bfloat16_rn(v);
    hi[i] = h;
    lo[i] = __float2bfloat16_rn(v - __bfloat162float(h));
}

// conv + silu + C-split; block col 9 additionally runs dt preprocessing
__global__ __launch_bounds__(256) void conv_silu_kernel(
    const float* __restrict__ cw, const float* __restrict__ cb,
    const float* __restrict__ dt_bias, const float* __restrict__ A_log)
{
    int row = blockIdx.y;
    if (blockIdx.x == 9) {
        if (threadIdx.x < 32) {
            int hh = threadIdx.x;
            float v = g_zx[(size_t)row * D_IN_PROJ + (D_INNER + CONV_DIM) + hh] + dt_bias[hh];
            float sp = (v > 20.f) ? v : log1pf(expf(v));
            g_dtp[row * NHEADS + hh] = sp;
            g_dA[row * NHEADS + hh] = expf(-expf(A_log[hh]) * sp);
        }
        return;
    }
    int c = blockIdx.x * 256 + threadIdx.x;
    int t = row & (SEQLEN - 1);
    float4 w = *(const float4*)(cw + c * 4);
    const float* wv = (const float*)&w;
    const float* col = g_zx + (size_t)row * D_IN_PROJ + D_INNER + c;
    float s = 0.f;
#pragma unroll
    for (int j = 0; j < 4; j++) {
        int tt = t - 3 + j;
        if (tt >= 0) s = fmaf(wv[j], col[(j - 3) * D_IN_PROJ], s);
    }
    s += cb[c];
    float val = s / (1.f + expf(-s));
    g_xconv[(size_t)row * CONV_DIM + c] = val;
    if (c >= D_INNER + D_STATE) {
        int n = c - (D_INNER + D_STATE);
        __nv_bfloat16 h = __float2bfloat16_rn(val);
        g_cbh[(size_t)row * 128 + n] = h;
        g_cbl[(size_t)row * 128 + n] = __float2bfloat16_rn(val - __bfloat162float(h));
    }
}

// =====================================================================
// Phase 1: local chunk scan (R13 exact config: 4-slot ring)
// =====================================================================
__global__ __launch_bounds__(128) void scan_local_kernel(const float* __restrict__ Dv)
{
    const int bx = blockIdx.x;
    const int chunk = bx & (NCHUNK - 1);
    const int h  = (bx >> 4) & 31;
    const int bi = bx >> 9;
    const int tid = threadIdx.x;
    const int pg = tid >> 3;
    const int ng = tid & 7;

    __shared__ __align__(16) float sB[4][4][128];
    __shared__ __align__(16) float sC[4][4][128];
    __shared__ __align__(16) float sxs[4][4][64];
    __shared__ __align__(16) float ssc[4][4][2];

    int fof[4];
#pragma unroll
    for (int j = 0; j < 4; j++) fof[j] = ng * 16 + ((j + (ng >> 1)) & 3) * 4;

    ull S[4][8];
#pragma unroll
    for (int p = 0; p < 4; p++)
#pragma unroll
        for (int j = 0; j < 8; j++) S[p][j] = 0ULL;

    const float Dh = Dv[h];
    const float* xcb = g_xconv + (size_t)bi * SEQLEN * CONV_DIM;
    const float* dAb = g_dA  + (size_t)bi * SEQLEN * NHEADS + h;
    const float* dtb = g_dtp + (size_t)bi * SEQLEN * NHEADS + h;
    const int t0 = chunk * CHLEN;

    auto stage4 = [&](int t, int pi) {
#pragma unroll
        for (int k = 0; k < 3; k++) {
            int c = tid + k * 128;
            if (c >= 328) break;
            int s = c / 82;
            int cc = c - s * 82;
            const float* rowp = xcb + (size_t)(t + s) * CONV_DIM;
            if (cc < 32)       cp_async16(smem_u32(&sB[pi][s][cc * 4]),  rowp + D_INNER + cc * 4, 16);
            else if (cc < 64)  cp_async16(smem_u32(&sC[pi][s][(cc - 32) * 4]), rowp + D_INNER + D_STATE + (cc - 32) * 4, 16);
            else if (cc < 80)  cp_async16(smem_u32(&sxs[pi][s][(cc - 64) * 4]), rowp + h * 64 + (cc - 64) * 4, 16);
            else if (cc == 80) cp_async4(smem_u32(&ssc[pi][s][0]), dAb + (size_t)(t + s) * NHEADS);
            else               cp_async4(smem_u32(&ssc[pi][s][1]), dtb + (size_t)(t + s) * NHEADS);
        }
    };

    stage4(t0,      0); cp_commit();
    stage4(t0 + 4,  1); cp_commit();
    stage4(t0 + 8,  2); cp_commit();
    stage4(t0 + 12, 3); cp_commit();

    float* yout = g_y + (size_t)bi * SEQLEN * D_INNER + h * 64 + pg * 4;
    float* cdout = g_cd + ((size_t)bi * NHEADS + h) * SEQLEN;
    float cdv = 1.f;

    const int NITER = CHLEN / 4;
    for (int it = 0; it < NITER; it++) {
        const int t = t0 + it * 4;
        const int pi = it & 3;
        cp_wait<3>();
        __syncthreads();

        float2 sc[4];
        float4 xs[4];
#pragma unroll
        for (int s = 0; s < 4; s++) {
            sc[s] = *(const float2*)&ssc[pi][s][0];
            xs[s] = *(const float4*)&sxs[pi][s][pg * 4];
        }

        float yv[4][4];
#pragma unroll
        for (int s = 0; s < 4; s++) {
            float4 B4[4], C4[4];
#pragma unroll
            for (int j = 0; j < 4; j++) {
                B4[j] = *(const float4*)(&sB[pi][s][0] + fof[j]);
                C4[j] = *(const float4*)(&sC[pi][s][0] + fof[j]);
            }
            const ull dA2 = f2pack(sc[s].x);
            const float dtv = sc[s].y;
            cdv *= sc[s].x;
            if (tid == 0) cdout[t + s] = cdv;
#pragma unroll
            for (int p = 0; p < 4; p++) {
                const float xv = ((const float*)&xs[s])[p];
                const ull xdt2 = f2pack(xv * dtv);
                ull a0 = 0ULL, a1 = 0ULL;
#pragma unroll
                for (int j = 0; j < 4; j++) {
                    const ull b0 = ((const ull*)&B4[j])[0];
                    const ull b1 = ((const ull*)&B4[j])[1];
                    const ull c0 = ((const ull*)&C4[j])[0];
                    const ull c1 = ((const ull*)&C4[j])[1];
                    S[p][2 * j]     = f2fma(dA2, S[p][2 * j],     f2mul(xdt2, b0));
                    S[p][2 * j + 1] = f2fma(dA2, S[p][2 * j + 1], f2mul(xdt2, b1));
                    if (j == 0) { a0 = f2mul(S[p][0], c0); a1 = f2mul(S[p][1], c1); }
                    else        { a0 = f2fma(S[p][2 * j], c0, a0); a1 = f2fma(S[p][2 * j + 1], c1, a1); }
                }
                yv[p][s] = f2sum(a0) + f2sum(a1);
            }
        }

#pragma unroll
        for (int o = 1; o < 8; o <<= 1) {
#pragma unroll
            for (int p = 0; p < 4; p++)
#pragma unroll
                for (int s = 0; s < 4; s++)
                    yv[p][s] += __shfl_xor_sync(0xffffffffu, yv[p][s], o);
        }
        if (ng == 0) {
#pragma unroll
            for (int s = 0; s < 4; s++) {
                float4 v;
                v.x = fmaf(Dh, ((const float*)&xs[s])[0], yv[0][s]);
                v.y = fmaf(Dh, ((const float*)&xs[s])[1], yv[1][s]);
                v.z = fmaf(Dh, ((const float*)&xs[s])[2], yv[2][s]);
                v.w = fmaf(Dh, ((const float*)&xs[s])[3], yv[3][s]);
                *(float4*)(yout + (size_t)(t + s) * D_INNER) = v;
            }
        }
        __syncthreads();
        if (it + 4 < NITER) stage4(t + 16, pi);
        cp_commit();
    }

    float* slb = g_Sloc + (((size_t)(bi * NHEADS + h) * NCHUNK + chunk) * 64 + pg * 4) * 128 + ng * 16;
#pragma unroll
    for (int p = 0; p < 4; p++)
#pragma unroll
        for (int j = 0; j < 4; j++) {
            int m = (j + (ng >> 1)) & 3;
            *(ull*)(slb + p * 128 + m * 4)     = S[p][2 * j];
            *(ull*)(slb + p * 128 + m * 4 + 2) = S[p][2 * j + 1];
        }
}

// =====================================================================
// Phase 2: sequential chunk-state combine (128 blocks = (b,h) x n-half)
// =====================================================================
__global__ __launch_bounds__(256) void combine_kernel()
{
    const int bh = blockIdx.x >> 1;
    const int half = blockIdx.x & 1;
    const int tid = threadIdx.x;
    const int base = half * 2048;
    const ull* sl = (const ull*)(g_Sloc + (size_t)bh * NCHUNK * 8192);
    uint32_t* sh  = (uint32_t*)g_ssh + (size_t)bh * NCHUNK * 4096;
    uint32_t* slo = (uint32_t*)g_ssl + (size_t)bh * NCHUNK * 4096;
    const float* cdp = g_cd + (size_t)bh * SEQLEN;

    ull s[8];
#pragma unroll
    for (int k = 0; k < 8; k++) s[k] = 0ULL;

    for (int j = 0; j < NCHUNK; j++) {
#pragma unroll
        for (int k = 0; k < 8; k++) {
            uint32_t hh, ll;
            splitull(s[k], hh, ll);
            sh [(size_t)j * 4096 + base + tid + k * 256] = hh;
            slo[(size_t)j * 4096 + base + tid + k * 256] = ll;
        }
        const ull cd2 = f2pack(cdp[j * CHLEN + CHLEN - 1]);
#pragma unroll
        for (int k = 0; k < 8; k++)
            s[k] = f2fma(cd2, s[k], sl[(size_t)j * 4096 + base + tid + k * 256]);
    }
}

// =====================================================================
// Phase 3 (tensorized correction, unchanged)
// =====================================================================
#define CR_CH 0
#define CR_CL 34816
#define CR_SH 69632
#define CR_SL 87040
#define CR_CD 104448
#define CR_SMEM 104960

__global__ __launch_bounds__(128) void correct_mma_kernel()
{
    extern __shared__ char sm[];
    const uint32_t smb = smem_u32(sm);
    const int bx = blockIdx.x;
    const int chunk = bx % (NCHUNK - 1) + 1;
    const int h  = (bx / (NCHUNK - 1)) % NHEADS;
    const int bi = bx / ((NCHUNK - 1) * NHEADS);
    const int tid = threadIdx.x;
    const int wid = tid >> 5;
    const int lane = tid & 31;
    const int t0 = chunk * CHLEN;
    const size_t bh = (size_t)bi * NHEADS + h;

    const __nv_bfloat16* Cgh = g_cbh + ((size_t)bi * SEQLEN + t0) * 128;
    const __nv_bfloat16* Cgl = g_cbl + ((size_t)bi * SEQLEN + t0) * 128;
    const __nv_bfloat16* Sgh = g_ssh + (bh * NCHUNK + chunk) * 8192;
    const __nv_bfloat16* Sgl = g_ssl + (bh * NCHUNK + chunk) * 8192;

#pragma unroll
    for (int i = 0; i < 16; i++) {
        int id = tid + i * 128;
        int row = id >> 4, cc = id & 15;
        cp_async16(smb + CR_CH + row * 272 + cc * 16, Cgh + row * 128 + cc * 8, 16);
        cp_async16(smb + CR_CL + row * 272 + cc * 16, Cgl + row * 128 + cc * 8, 16);
    }
#pragma unroll
    for (int i = 0; i < 8; i++) {
        int id = tid + i * 128;
        int row = id >> 4, cc = id & 15;
        cp_async16(smb + CR_SH + row * 272 + cc * 16, Sgh + row * 128 + cc * 8, 16);
        cp_async16(smb + CR_SL + row * 272 + cc * 16, Sgl + row * 128 + cc * 8, 16);
    }
    cp_async4(smb + CR_CD + tid * 4, g_cd + bh * SEQLEN + t0 + tid);
    cp_commit();
    cp_wait<0>();
    __syncthreads();

    const int jj = lane >> 3;
    const int lr = lane & 7;
    const int aRow = (jj & 1) * 8 + lr;
    const int aColB = (jj >> 1) * 16;
    const int bRow = (jj >> 1) * 8 + lr;
    const int bColB = (jj & 1) * 16;
    const int wm = wid * 32;

    float acc[2][8][4];
#pragma unroll
    for (int mt = 0; mt < 2; mt++)
#pragma unroll
        for (int j = 0; j < 8; j++)
#pragma unroll
            for (int e = 0; e < 4; e++) acc[mt][j][e] = 0.f;

#pragma unroll
    for (int ks = 0; ks < 8; ks++) {
        uint32_t ah[2][4], al[2][4], bh4[4][4], bl4[4][4];
#pragma unroll
        for (int mt = 0; mt < 2; mt++) {
            uint32_t off = (uint32_t)((wm + mt * 16 + aRow) * 272 + ks * 32 + aColB);
            ldsm4(ah[mt], smb + CR_CH + off);
            ldsm4(al[mt], smb + CR_CL + off);
        }
#pragma unroll
        for (int pn = 0; pn < 4; pn++) {
            uint32_t off = (uint32_t)((pn * 16 + bRow) * 272 + ks * 32 + bColB);
            ldsm4(bh4[pn], smb + CR_SH + off);
            ldsm4(bl4[pn], smb + CR_SL + off);
        }
#pragma unroll
        for (int mt = 0; mt < 2; mt++)
#pragma unroll
            for (int j = 0; j < 8; j++) {
                const uint32_t* bf  = bh4[j >> 1] + (j & 1) * 2;
                const uint32_t* bl2 = bl4[j >> 1] + (j & 1) * 2;
                mma16816(acc[mt][j], ah[mt], bf);
                mma16816(acc[mt][j], al[mt], bf);
                mma16816(acc[mt][j], ah[mt], bl2);
            }
    }

    const float* cds = (const float*)(sm + CR_CD);
    float* yb = g_y + ((size_t)bi * SEQLEN + t0) * D_INNER + h * 64;
    const int r0 = wm + (lane >> 2);
#pragma unroll
    for (int mt = 0; mt < 2; mt++) {
#pragma unroll
        for (int j = 0; j < 8; j++) {
            int col = (j >> 1) * 16 + (j & 1) * 8 + (lane & 3) * 2;
            int r1 = r0 + mt * 16;
            int r2 = r1 + 8;
            float2 y1 = *(float2*)(yb + (size_t)r1 * D_INNER + col);
            float2 y2 = *(float2*)(yb + (size_t)r2 * D_INNER + col);
            float c1 = cds[r1], c2 = cds[r2];
            y1.x = fmaf(c1, acc[mt][j][0], y1.x);
            y1.y = fmaf(c1, acc[mt][j][1], y1.y);
            y2.x = fmaf(c2, acc[mt][j][2], y2.x);
            y2.y = fmaf(c2, acc[mt][j][3], y2.y);
            *(float2*)(yb + (size_t)r1 * D_INNER + col) = y1;
            *(float2*)(yb + (size_t)r2 * D_INNER + col) = y2;
        }
    }
}

// =====================================================================
__global__ __launch_bounds__(256) void gatenorm_kernel(const float* __restrict__ nw)
{
    int row = blockIdx.x;
    int tid = threadIdx.x;
    const float* yr = g_y + (size_t)row * D_INNER;
    const float* zr = g_zx + (size_t)row * D_IN_PROJ;
    float v[8];
    float ss = 0.f;
#pragma unroll
    for (int i = 0; i < 8; i++) {
        int c = tid + i * 256;
        float z = zr[c];
        float val = yr[c] * (z / (1.f + expf(-z)));
        v[i] = val;
        ss = fmaf(val, val, ss);
    }
#pragma unroll
    for (int o = 16; o; o >>= 1) ss += __shfl_xor_sync(0xffffffffu, ss, o);
    __shared__ float red[8];
    if ((tid & 31) == 0) red[tid >> 5] = ss;
    __syncthreads();
    float tot = red[0] + red[1] + red[2] + red[3] + red[4] + red[5] + red[6] + red[7];
    float scale = rsqrtf(tot * (1.0f / 2048.0f) + 1e-5f);
#pragma unroll
    for (int i = 0; i < 8; i++) {
        int c = tid + i * 256;
        float val = v[i] * scale * nw[c];
        __nv_bfloat16 h = __float2bfloat16_rn(val);
        g_nh[(size_t)row * D_INNER + c] = h;
        g_nl[(size_t)row * D_INNER + c] = __float2bfloat16_rn(val - __bfloat162float(h));
    }
}

// =====================================================================
extern "C" void kernel_launch(void* const* d_in, const int* in_sizes, int n_in,
                              void* d_out, int out_size)
{
    const float* x          = (const float*)d_in[0];
    const float* in_proj_w  = (const float*)d_in[1];
    const float* conv_w     = (const float*)d_in[2];
    const float* conv_b     = (const float*)d_in[3];
    const float* dt_bias    = (const float*)d_in[4];
    const float* A_log      = (const float*)d_in[5];
    const float* Dv         = (const float*)d_in[6];
    const float* norm_w     = (const float*)d_in[7];
    const float* out_proj_w = (const float*)d_in[8];
    float* out = (float*)d_out;

    float *zx;
    __nv_bfloat16 *xh, *xl, *w1h, *w1l, *w2h, *w2l, *nh, *nl;
    cudaGetSymbolAddress((void**)&zx, g_zx);
    cudaGetSymbolAddress((void**)&xh, g_xhb);
    cudaGetSymbolAddress((void**)&xl, g_xlb);
    cudaGetSymbolAddress((void**)&w1h, g_w1h);
    cudaGetSymbolAddress((void**)&w1l, g_w1l);
    cudaGetSymbolAddress((void**)&w2h, g_w2h);
    cudaGetSymbolAddress((void**)&w2l, g_w2l);
    cudaGetSymbolAddress((void**)&nh, g_nh);
    cudaGetSymbolAddress((void**)&nl, g_nl);

    cudaFuncSetAttribute(gemm_mma, cudaFuncAttributeMaxDynamicSharedMemorySize, GSMEM);
    cudaFuncSetAttribute(correct_mma_kernel, cudaFuncAttributeMaxDynamicSharedMemorySize, CR_SMEM);

    const int SPLIT_TOT = SPLIT_N0 + SPLIT_N1 + SPLIT_N2;
    split_all_kernel<<<(SPLIT_TOT + 255) / 256, 256>>>(x, in_proj_w, out_proj_w);

    gemm_mma<<<dim3((D_IN_PROJ + 127) / 128, BL / 128), 256, GSMEM>>>(
        xh, xl, w1h, w1l, zx, nullptr, BL, D_IN_PROJ, D_MODEL);

    conv_silu_kernel<<<dim3(10, BL), 256>>>(conv_w, conv_b, dt_bias, A_log);

    scan_local_kernel<<<BATCH * NHEADS * NCHUNK, 128>>>(Dv);
    combine_kernel<<<BATCH * NHEADS * 2, 256>>>();
    correct_mma_kernel<<<BATCH * NHEADS * (NCHUNK - 1), 128, CR_SMEM>>>();

    gatenorm_kernel<<<BL, 256>>>(norm_w);

    gemm_mma<<<dim3(D_MODEL / 128, BL / 128), 256, GSMEM>>>(
        nh, nl, w2h, w2l, out, x, BL, D_MODEL, D_INNER);
}

// round 16
// speedup vs baseline: 1.0619x; 1.0334x over previous
#include <cuda_runtime.h>
#include <cuda_bf16.h>
#include <cstdint>

typedef unsigned long long ull;

#define D_MODEL   1024
#define D_STATE   128
#define D_INNER   2048
#define NHEADS    32
#define HEADDIM   64
#define CONV_DIM  2304
#define D_IN_PROJ 4384
#define SEQLEN    2048
#define BATCH     2
#define BL        (BATCH * SEQLEN)   // 4096

#define NCHUNK    16
#define CHLEN     128
#define CT        16                 // conv timestep tile

// ---------------- device scratch ----------------
__device__ float g_zx[(size_t)BL * D_IN_PROJ];
__device__ float g_xconv[(size_t)BL * CONV_DIM];
__device__ float g_dtp[(size_t)BL * NHEADS];
__device__ float g_dA[(size_t)BL * NHEADS];
__device__ float g_y[(size_t)BL * D_INNER];
__device__ float g_cd[(size_t)BATCH * NHEADS * SEQLEN];
__device__ float g_Sloc[(size_t)BATCH * NHEADS * NCHUNK * 64 * 128];
__device__ __nv_bfloat16 g_ssh[(size_t)BATCH * NHEADS * NCHUNK * 64 * 128];
__device__ __nv_bfloat16 g_ssl[(size_t)BATCH * NHEADS * NCHUNK * 64 * 128];
__device__ __nv_bfloat16 g_cbh[(size_t)BL * 128];
__device__ __nv_bfloat16 g_cbl[(size_t)BL * 128];
__device__ __nv_bfloat16 g_xhb[(size_t)BL * D_MODEL];
__device__ __nv_bfloat16 g_xlb[(size_t)BL * D_MODEL];
__device__ __nv_bfloat16 g_w1h[(size_t)D_IN_PROJ * D_MODEL];
__device__ __nv_bfloat16 g_w1l[(size_t)D_IN_PROJ * D_MODEL];
__device__ __nv_bfloat16 g_w2h[(size_t)D_MODEL * D_INNER];
__device__ __nv_bfloat16 g_w2l[(size_t)D_MODEL * D_INNER];
__device__ __nv_bfloat16 g_nh[(size_t)BL * D_INNER];
__device__ __nv_bfloat16 g_nl[(size_t)BL * D_INNER];

// ---------------- PTX helpers ----------------
__device__ __forceinline__ uint32_t smem_u32(const void* p) {
    return (uint32_t)__cvta_generic_to_shared(p);
}
__device__ __forceinline__ void cp_async16(uint32_t dst, const void* src, int nbytes) {
    asm volatile("cp.async.cg.shared.global [%0], [%1], 16, %2;" :: "r"(dst), "l"(src), "r"(nbytes) : "memory");
}
__device__ __forceinline__ void cp_async4(uint32_t dst, const void* src) {
    asm volatile("cp.async.ca.shared.global [%0], [%1], 4;" :: "r"(dst), "l"(src) : "memory");
}
__device__ __forceinline__ void cp_commit() { asm volatile("cp.async.commit_group;" ::: "memory"); }
template<int N> __device__ __forceinline__ void cp_wait() { asm volatile("cp.async.wait_group %0;" :: "n"(N) : "memory"); }

__device__ __forceinline__ void ldsm4(uint32_t* r, uint32_t addr) {
    asm volatile("ldmatrix.sync.aligned.m8n8.x4.shared.b16 {%0,%1,%2,%3}, [%4];"
        : "=r"(r[0]), "=r"(r[1]), "=r"(r[2]), "=r"(r[3]) : "r"(addr));
}
__device__ __forceinline__ void mma16816(float* d, const uint32_t* a, const uint32_t* b) {
    asm volatile("mma.sync.aligned.m16n8k16.row.col.f32.bf16.bf16.f32 "
        "{%0,%1,%2,%3}, {%4,%5,%6,%7}, {%8,%9}, {%0,%1,%2,%3};"
        : "+f"(d[0]), "+f"(d[1]), "+f"(d[2]), "+f"(d[3])
        : "r"(a[0]), "r"(a[1]), "r"(a[2]), "r"(a[3]), "r"(b[0]), "r"(b[1]));
}

__device__ __forceinline__ ull f2fma(ull a, ull b, ull c) { ull d; asm("fma.rn.f32x2 %0, %1, %2, %3;" : "=l"(d) : "l"(a), "l"(b), "l"(c)); return d; }
__device__ __forceinline__ ull f2mul(ull a, ull b) { ull d; asm("mul.rn.f32x2 %0, %1, %2;" : "=l"(d) : "l"(a), "l"(b)); return d; }
__device__ __forceinline__ ull f2pack(float x) { ull d; asm("mov.b64 %0, {%1, %2};" : "=l"(d) : "f"(x), "f"(x)); return d; }
__device__ __forceinline__ float f2sum(ull a) { float lo, hi; asm("mov.b64 {%0, %1}, %2;" : "=f"(lo), "=f"(hi) : "l"(a)); return lo + hi; }

__device__ __forceinline__ void splitull(ull v, uint32_t& hh, uint32_t& ll) {
    float a, b;
    asm("mov.b64 {%0, %1}, %2;" : "=f"(a), "=f"(b) : "l"(v));
    __nv_bfloat16 ha = __float2bfloat16_rn(a), hb = __float2bfloat16_rn(b);
    __nv_bfloat16 la = __float2bfloat16_rn(a - __bfloat162float(ha));
    __nv_bfloat16 lb = __float2bfloat16_rn(b - __bfloat162float(hb));
    uint16_t uha = *(uint16_t*)&ha, uhb = *(uint16_t*)&hb;
    uint16_t ula = *(uint16_t*)&la, ulb = *(uint16_t*)&lb;
    hh = (uint32_t)uha | ((uint32_t)uhb << 16);
    ll = (uint32_t)ula | ((uint32_t)ulb << 16);
}

// =====================================================================
// bf16 3-term-split GEMM: BM=128 BN=128 BK=32, 2-stage, 2 CTAs/SM,
// SINGLE __syncthreads per BK-iter.
// =====================================================================
#define ROW_B   80
#define TILE_B  (128 * ROW_B)
#define STAGE_B (4 * TILE_B)
#define GSMEM   (2 * STAGE_B)

__global__ __launch_bounds__(256, 2) void gemm_mma(
    const __nv_bfloat16* __restrict__ Ah, const __nv_bfloat16* __restrict__ Al,
    const __nv_bfloat16* __restrict__ Bh, const __nv_bfloat16* __restrict__ Bl,
    float* __restrict__ C, const float* __restrict__ resid,
    int M, int N, int K)
{
    extern __shared__ char sm[];
    const uint32_t smb = smem_u32(sm);
    const int tid  = threadIdx.x;
    const int wid  = tid >> 5;
    const int lane = tid & 31;
    const int bm = blockIdx.y * 128;
    const int bn = blockIdx.x * 128;
    const int wm = (wid & 3) * 32;
    const int wn = (wid >> 2) * 64;

    const __nv_bfloat16* srcs[4] = {Ah, Al, Bh, Bl};

    auto stage = [&](int it, int buf) {
        const int k0 = it * 32;
#pragma unroll
        for (int i = 0; i < 8; i++) {
            int f = tid + i * 256;
            int tsel = f >> 9;
            int c = f & 511;
            int r = c >> 2;
            int cc = c & 3;
            uint32_t dst = smb + buf * STAGE_B + tsel * TILE_B + r * ROW_B + cc * 16;
            int row = (tsel < 2) ? (bm + r) : (bn + r);
            int nb = 16;
            if (tsel >= 2 && row >= N) { row = bn; nb = 0; }
            cp_async16(dst, srcs[tsel] + (size_t)row * K + k0 + cc * 8, nb);
        }
    };

    const int jj = lane >> 3;
    const int lr = lane & 7;
    const int aRow = (jj & 1) * 8 + lr;
    const int aColB = (jj >> 1) * 16;
    const int bRow = (jj >> 1) * 8 + lr;
    const int bColB = (jj & 1) * 16;

    float acc[2][8][4];
#pragma unroll
    for (int mt = 0; mt < 2; mt++)
#pragma unroll
        for (int j = 0; j < 8; j++)
#pragma unroll
            for (int e = 0; e < 4; e++) acc[mt][j][e] = 0.f;

    const int NIT = K >> 5;
    stage(0, 0);
    cp_commit();

    for (int it = 0; it < NIT; it++) {
        const int buf = it & 1;
        cp_wait<0>();
        __syncthreads();
        // stage(it+1) writes buf^1; its prior readers finished at iter it-1,
        // separated by the sync above. Issue before compute for overlap.
        if (it + 1 < NIT) { stage(it + 1, buf ^ 1); cp_commit(); }

        const uint32_t ab  = smb + buf * STAGE_B;
        const uint32_t alb = ab + TILE_B;
        const uint32_t bhb = ab + 2 * TILE_B;
        const uint32_t blb = ab + 3 * TILE_B;

#pragma unroll
        for (int ks = 0; ks < 2; ks++) {
            uint32_t ah[2][4], alf[2][4], bh[4][4], blf[4][4];
#pragma unroll
            for (int mt = 0; mt < 2; mt++) {
                uint32_t off = (uint32_t)((wm + mt * 16 + aRow) * ROW_B + ks * 32 + aColB);
                ldsm4(ah[mt],  ab  + off);
                ldsm4(alf[mt], alb + off);
            }
#pragma unroll
            for (int pn = 0; pn < 4; pn++) {
                uint32_t off = (uint32_t)((wn + pn * 16 + bRow) * ROW_B + ks * 32 + bColB);
                ldsm4(bh[pn],  bhb + off);
                ldsm4(blf[pn], blb + off);
            }
#pragma unroll
            for (int mt = 0; mt < 2; mt++)
#pragma unroll
                for (int j = 0; j < 8; j++) {
                    const uint32_t* bf  = bh[j >> 1] + (j & 1) * 2;
                    const uint32_t* bl2 = blf[j >> 1] + (j & 1) * 2;
                    mma16816(acc[mt][j], ah[mt],  bf);
                    mma16816(acc[mt][j], alf[mt], bf);
                    mma16816(acc[mt][j], ah[mt],  bl2);
                }
        }
    }

    const int r0 = bm + wm + (lane >> 2);
#pragma unroll
    for (int mt = 0; mt < 2; mt++) {
#pragma unroll
        for (int j = 0; j < 8; j++) {
            int col = bn + wn + (j >> 1) * 16 + (j & 1) * 8 + (lane & 3) * 2;
            if (col < N) {
                int r1 = r0 + mt * 16;
                int r2 = r1 + 8;
                float2 v1 = make_float2(acc[mt][j][0], acc[mt][j][1]);
                float2 v2 = make_float2(acc[mt][j][2], acc[mt][j][3]);
                if (resid) {
                    float2 q1 = *(const float2*)(resid + (size_t)r1 * N + col);
                    float2 q2 = *(const float2*)(resid + (size_t)r2 * N + col);
                    v1.x += q1.x; v1.y += q1.y; v2.x += q2.x; v2.y += q2.y;
                }
                *(float2*)(C + (size_t)r1 * N + col) = v1;
                *(float2*)(C + (size_t)r2 * N + col) = v2;
            }
        }
    }
}

// =====================================================================
// fused operand splits: x, w1, w2 in one launch
// =====================================================================
#define SPLIT_N0 (BL * D_MODEL)
#define SPLIT_N1 (D_IN_PROJ * D_MODEL)
#define SPLIT_N2 (D_MODEL * D_INNER)

__global__ __launch_bounds__(256) void split_all_kernel(
    const float* __restrict__ x, const float* __restrict__ w1,
    const float* __restrict__ w2)
{
    int i = blockIdx.x * 256 + threadIdx.x;
    const float* src;
    __nv_bfloat16 *hi, *lo;
    if (i < SPLIT_N0) { src = x; hi = g_xhb; lo = g_xlb; }
    else if (i < SPLIT_N0 + SPLIT_N1) { i -= SPLIT_N0; src = w1; hi = g_w1h; lo = g_w1l; }
    else if (i < SPLIT_N0 + SPLIT_N1 + SPLIT_N2) { i -= SPLIT_N0 + SPLIT_N1; src = w2; hi = g_w2h; lo = g_w2l; }
    else return;
    float v = src[i];
    __nv_bfloat16 h = __float2bfloat16_rn(v);
    hi[i] = h;
    lo[i] = __float2bfloat16_rn(v - __bfloat162float(h));
}

// =====================================================================
// conv + silu + C-split, smem-tiled: block = 256 channels x 16 timesteps.
// Loads 19 rows once (1.19x amplification vs 4x). Block x==9 does dt.
// =====================================================================
__global__ __launch_bounds__(256) void conv_silu_kernel(
    const float* __restrict__ cw, const float* __restrict__ cb,
    const float* __restrict__ dt_bias, const float* __restrict__ A_log)
{
    const int tid = threadIdx.x;
    const int by = blockIdx.y;              // 0..255
    const int bi = by >> 7;                 // batch
    const int t0 = (by & 127) * CT;         // timestep tile start within seq

    if (blockIdx.x == 9) {
        // dt path for rows t0..t0+CT-1 (CT*32 = 512 values)
#pragma unroll
        for (int k = 0; k < 2; k++) {
            int i = tid + k * 256;
            int tt = t0 + (i >> 5);
            int hh = i & 31;
            int row = bi * SEQLEN + tt;
            float v = g_zx[(size_t)row * D_IN_PROJ + (D_INNER + CONV_DIM) + hh] + dt_bias[hh];
            float sp = (v > 20.f) ? v : log1pf(expf(v));
            g_dtp[row * NHEADS + hh] = sp;
            g_dA[row * NHEADS + hh] = expf(-expf(A_log[hh]) * sp);
        }
        return;
    }

    __shared__ __align__(16) float sx[CT + 3][256];
    const int c0 = blockIdx.x * 256;

    // stage rows t0-3 .. t0+CT-1 (19 rows x 64 float4)
#pragma unroll
    for (int k = 0; k < 5; k++) {
        int i = tid + k * 256;
        if (i >= (CT + 3) * 64) break;
        int r = i >> 6;
        int cc = (i & 63) * 4;
        int tt = t0 - 3 + r;
        if (tt >= 0) {
            cp_async16(smem_u32(&sx[r][cc]),
                       g_zx + (size_t)(bi * SEQLEN + tt) * D_IN_PROJ + D_INNER + c0 + cc, 16);
        } else {
            *(float4*)&sx[r][cc] = make_float4(0.f, 0.f, 0.f, 0.f);
        }
    }
    cp_commit();
    cp_wait<0>();
    __syncthreads();

    const int c = c0 + tid;
    const float4 w = *(const float4*)(cw + c * 4);
    const float bias = cb[c];
    const bool isC = (c >= D_INNER + D_STATE);
    const int n = c - (D_INNER + D_STATE);

#pragma unroll
    for (int k = 0; k < CT; k++) {
        float s = 0.f;
        s = fmaf(w.x, sx[k][tid], s);
        s = fmaf(w.y, sx[k + 1][tid], s);
        s = fmaf(w.z, sx[k + 2][tid], s);
        s = fmaf(w.w, sx[k + 3][tid], s);
        s += bias;
        float val = s / (1.f + expf(-s));
        int row = bi * SEQLEN + t0 + k;
        g_xconv[(size_t)row * CONV_DIM + c] = val;
        if (isC) {
            __nv_bfloat16 h = __float2bfloat16_rn(val);
            g_cbh[(size_t)row * 128 + n] = h;
            g_cbl[(size_t)row * 128 + n] = __float2bfloat16_rn(val - __bfloat162float(h));
        }
    }
}

// =====================================================================
// Phase 1: local chunk scan (R15 exact config)
// =====================================================================
__global__ __launch_bounds__(128) void scan_local_kernel(const float* __restrict__ Dv)
{
    const int bx = blockIdx.x;
    const int chunk = bx & (NCHUNK - 1);
    const int h  = (bx >> 4) & 31;
    const int bi = bx >> 9;
    const int tid = threadIdx.x;
    const int pg = tid >> 3;
    const int ng = tid & 7;

    __shared__ __align__(16) float sB[4][4][128];
    __shared__ __align__(16) float sC[4][4][128];
    __shared__ __align__(16) float sxs[4][4][64];
    __shared__ __align__(16) float ssc[4][4][2];

    int fof[4];
#pragma unroll
    for (int j = 0; j < 4; j++) fof[j] = ng * 16 + ((j + (ng >> 1)) & 3) * 4;

    ull S[4][8];
#pragma unroll
    for (int p = 0; p < 4; p++)
#pragma unroll
        for (int j = 0; j < 8; j++) S[p][j] = 0ULL;

    const float Dh = Dv[h];
    const float* xcb = g_xconv + (size_t)bi * SEQLEN * CONV_DIM;
    const float* dAb = g_dA  + (size_t)bi * SEQLEN * NHEADS + h;
    const float* dtb = g_dtp + (size_t)bi * SEQLEN * NHEADS + h;
    const int t0 = chunk * CHLEN;

    auto stage4 = [&](int t, int pi) {
#pragma unroll
        for (int k = 0; k < 3; k++) {
            int c = tid + k * 128;
            if (c >= 328) break;
            int s = c / 82;
            int cc = c - s * 82;
            const float* rowp = xcb + (size_t)(t + s) * CONV_DIM;
            if (cc < 32)       cp_async16(smem_u32(&sB[pi][s][cc * 4]),  rowp + D_INNER + cc * 4, 16);
            else if (cc < 64)  cp_async16(smem_u32(&sC[pi][s][(cc - 32) * 4]), rowp + D_INNER + D_STATE + (cc - 32) * 4, 16);
            else if (cc < 80)  cp_async16(smem_u32(&sxs[pi][s][(cc - 64) * 4]), rowp + h * 64 + (cc - 64) * 4, 16);
            else if (cc == 80) cp_async4(smem_u32(&ssc[pi][s][0]), dAb + (size_t)(t + s) * NHEADS);
            else               cp_async4(smem_u32(&ssc[pi][s][1]), dtb + (size_t)(t + s) * NHEADS);
        }
    };

    stage4(t0,      0); cp_commit();
    stage4(t0 + 4,  1); cp_commit();
    stage4(t0 + 8,  2); cp_commit();
    stage4(t0 + 12, 3); cp_commit();

    float* yout = g_y + (size_t)bi * SEQLEN * D_INNER + h * 64 + pg * 4;
    float* cdout = g_cd + ((size_t)bi * NHEADS + h) * SEQLEN;
    float cdv = 1.f;

    const int NITER = CHLEN / 4;
    for (int it = 0; it < NITER; it++) {
        const int t = t0 + it * 4;
        const int pi = it & 3;
        cp_wait<3>();
        __syncthreads();

        float2 sc[4];
        float4 xs[4];
#pragma unroll
        for (int s = 0; s < 4; s++) {
            sc[s] = *(const float2*)&ssc[pi][s][0];
            xs[s] = *(const float4*)&sxs[pi][s][pg * 4];
        }

        float yv[4][4];
#pragma unroll
        for (int s = 0; s < 4; s++) {
            float4 B4[4], C4[4];
#pragma unroll
            for (int j = 0; j < 4; j++) {
                B4[j] = *(const float4*)(&sB[pi][s][0] + fof[j]);
                C4[j] = *(const float4*)(&sC[pi][s][0] + fof[j]);
            }
            const ull dA2 = f2pack(sc[s].x);
            const float dtv = sc[s].y;
            cdv *= sc[s].x;
            if (tid == 0) cdout[t + s] = cdv;
#pragma unroll
            for (int p = 0; p < 4; p++) {
                const float xv = ((const float*)&xs[s])[p];
                const ull xdt2 = f2pack(xv * dtv);
                ull a0 = 0ULL, a1 = 0ULL;
#pragma unroll
                for (int j = 0; j < 4; j++) {
                    const ull b0 = ((const ull*)&B4[j])[0];
                    const ull b1 = ((const ull*)&B4[j])[1];
                    const ull c0v = ((const ull*)&C4[j])[0];
                    const ull c1v = ((const ull*)&C4[j])[1];
                    S[p][2 * j]     = f2fma(dA2, S[p][2 * j],     f2mul(xdt2, b0));
                    S[p][2 * j + 1] = f2fma(dA2, S[p][2 * j + 1], f2mul(xdt2, b1));
                    if (j == 0) { a0 = f2mul(S[p][0], c0v); a1 = f2mul(S[p][1], c1v); }
                    else        { a0 = f2fma(S[p][2 * j], c0v, a0); a1 = f2fma(S[p][2 * j + 1], c1v, a1); }
                }
                yv[p][s] = f2sum(a0) + f2sum(a1);
            }
        }

#pragma unroll
        for (int o = 1; o < 8; o <<= 1) {
#pragma unroll
            for (int p = 0; p < 4; p++)
#pragma unroll
                for (int s = 0; s < 4; s++)
                    yv[p][s] += __shfl_xor_sync(0xffffffffu, yv[p][s], o);
        }
        if (ng == 0) {
#pragma unroll
            for (int s = 0; s < 4; s++) {
                float4 v;
                v.x = fmaf(Dh, ((const float*)&xs[s])[0], yv[0][s]);
                v.y = fmaf(Dh, ((const float*)&xs[s])[1], yv[1][s]);
                v.z = fmaf(Dh, ((const float*)&xs[s])[2], yv[2][s]);
                v.w = fmaf(Dh, ((const float*)&xs[s])[3], yv[3][s]);
                *(float4*)(yout + (size_t)(t + s) * D_INNER) = v;
            }
        }
        __syncthreads();
        if (it + 4 < NITER) stage4(t + 16, pi);
        cp_commit();
    }

    float* slb = g_Sloc + (((size_t)(bi * NHEADS + h) * NCHUNK + chunk) * 64 + pg * 4) * 128 + ng * 16;
#pragma unroll
    for (int p = 0; p < 4; p++)
#pragma unroll
        for (int j = 0; j < 4; j++) {
            int m = (j + (ng >> 1)) & 3;
            *(ull*)(slb + p * 128 + m * 4)     = S[p][2 * j];
            *(ull*)(slb + p * 128 + m * 4 + 2) = S[p][2 * j + 1];
        }
}

// =====================================================================
// Phase 2: sequential chunk-state combine (128 blocks = (b,h) x n-half)
// =====================================================================
__global__ __launch_bounds__(256) void combine_kernel()
{
    const int bh = blockIdx.x >> 1;
    const int half = blockIdx.x & 1;
    const int tid = threadIdx.x;
    const int base = half * 2048;
    const ull* sl = (const ull*)(g_Sloc + (size_t)bh * NCHUNK * 8192);
    uint32_t* sh  = (uint32_t*)g_ssh + (size_t)bh * NCHUNK * 4096;
    uint32_t* slo = (uint32_t*)g_ssl + (size_t)bh * NCHUNK * 4096;
    const float* cdp = g_cd + (size_t)bh * SEQLEN;

    ull s[8];
#pragma unroll
    for (int k = 0; k < 8; k++) s[k] = 0ULL;

    for (int j = 0; j < NCHUNK; j++) {
#pragma unroll
        for (int k = 0; k < 8; k++) {
            uint32_t hh, ll;
            splitull(s[k], hh, ll);
            sh [(size_t)j * 4096 + base + tid + k * 256] = hh;
            slo[(size_t)j * 4096 + base + tid + k * 256] = ll;
        }
        const ull cd2 = f2pack(cdp[j * CHLEN + CHLEN - 1]);
#pragma unroll
        for (int k = 0; k < 8; k++)
            s[k] = f2fma(cd2, s[k], sl[(size_t)j * 4096 + base + tid + k * 256]);
    }
}

// =====================================================================
// Phase 3 (tensorized correction, unchanged)
// =====================================================================
#define CR_CH 0
#define CR_CL 34816
#define CR_SH 69632
#define CR_SL 87040
#define CR_CD 104448
#define CR_SMEM 104960

__global__ __launch_bounds__(128) void correct_mma_kernel()
{
    extern __shared__ char sm[];
    const uint32_t smb = smem_u32(sm);
    const int bx = blockIdx.x;
    const int chunk = bx % (NCHUNK - 1) + 1;
    const int h  = (bx / (NCHUNK - 1)) % NHEADS;
    const int bi = bx / ((NCHUNK - 1) * NHEADS);
    const int tid = threadIdx.x;
    const int wid = tid >> 5;
    const int lane = tid & 31;
    const int t0 = chunk * CHLEN;
    const size_t bh = (size_t)bi * NHEADS + h;

    const __nv_bfloat16* Cgh = g_cbh + ((size_t)bi * SEQLEN + t0) * 128;
    const __nv_bfloat16* Cgl = g_cbl + ((size_t)bi * SEQLEN + t0) * 128;
    const __nv_bfloat16* Sgh = g_ssh + (bh * NCHUNK + chunk) * 8192;
    const __nv_bfloat16* Sgl = g_ssl + (bh * NCHUNK + chunk) * 8192;

#pragma unroll
    for (int i = 0; i < 16; i++) {
        int id = tid + i * 128;
        int row = id >> 4, cc = id & 15;
        cp_async16(smb + CR_CH + row * 272 + cc * 16, Cgh + row * 128 + cc * 8, 16);
        cp_async16(smb + CR_CL + row * 272 + cc * 16, Cgl + row * 128 + cc * 8, 16);
    }
#pragma unroll
    for (int i = 0; i < 8; i++) {
        int id = tid + i * 128;
        int row = id >> 4, cc = id & 15;
        cp_async16(smb + CR_SH + row * 272 + cc * 16, Sgh + row * 128 + cc * 8, 16);
        cp_async16(smb + CR_SL + row * 272 + cc * 16, Sgl + row * 128 + cc * 8, 16);
    }
    cp_async4(smb + CR_CD + tid * 4, g_cd + bh * SEQLEN + t0 + tid);
    cp_commit();
    cp_wait<0>();
    __syncthreads();

    const int jj = lane >> 3;
    const int lr = lane & 7;
    const int aRow = (jj & 1) * 8 + lr;
    const int aColB = (jj >> 1) * 16;
    const int bRow = (jj >> 1) * 8 + lr;
    const int bColB = (jj & 1) * 16;
    const int wm = wid * 32;

    float acc[2][8][4];
#pragma unroll
    for (int mt = 0; mt < 2; mt++)
#pragma unroll
        for (int j = 0; j < 8; j++)
#pragma unroll
            for (int e = 0; e < 4; e++) acc[mt][j][e] = 0.f;

#pragma unroll
    for (int ks = 0; ks < 8; ks++) {
        uint32_t ah[2][4], al[2][4], bh4[4][4], bl4[4][4];
#pragma unroll
        for (int mt = 0; mt < 2; mt++) {
            uint32_t off = (uint32_t)((wm + mt * 16 + aRow) * 272 + ks * 32 + aColB);
            ldsm4(ah[mt], smb + CR_CH + off);
            ldsm4(al[mt], smb + CR_CL + off);
        }
#pragma unroll
        for (int pn = 0; pn < 4; pn++) {
            uint32_t off = (uint32_t)((pn * 16 + bRow) * 272 + ks * 32 + bColB);
            ldsm4(bh4[pn], smb + CR_SH + off);
            ldsm4(bl4[pn], smb + CR_SL + off);
        }
#pragma unroll
        for (int mt = 0; mt < 2; mt++)
#pragma unroll
            for (int j = 0; j < 8; j++) {
                const uint32_t* bf  = bh4[j >> 1] + (j & 1) * 2;
                const uint32_t* bl2 = bl4[j >> 1] + (j & 1) * 2;
                mma16816(acc[mt][j], ah[mt], bf);
                mma16816(acc[mt][j], al[mt], bf);
                mma16816(acc[mt][j], ah[mt], bl2);
            }
    }

    const float* cds = (const float*)(sm + CR_CD);
    float* yb = g_y + ((size_t)bi * SEQLEN + t0) * D_INNER + h * 64;
    const int r0 = wm + (lane >> 2);
#pragma unroll
    for (int mt = 0; mt < 2; mt++) {
#pragma unroll
        for (int j = 0; j < 8; j++) {
            int col = (j >> 1) * 16 + (j & 1) * 8 + (lane & 3) * 2;
            int r1 = r0 + mt * 16;
            int r2 = r1 + 8;
            float2 y1 = *(float2*)(yb + (size_t)r1 * D_INNER + col);
            float2 y2 = *(float2*)(yb + (size_t)r2 * D_INNER + col);
            float c1 = cds[r1], c2 = cds[r2];
            y1.x = fmaf(c1, acc[mt][j][0], y1.x);
            y1.y = fmaf(c1, acc[mt][j][1], y1.y);
            y2.x = fmaf(c2, acc[mt][j][2], y2.x);
            y2.y = fmaf(c2, acc[mt][j][3], y2.y);
            *(float2*)(yb + (size_t)r1 * D_INNER + col) = y1;
            *(float2*)(yb + (size_t)r2 * D_INNER + col) = y2;
        }
    }
}

// =====================================================================
__global__ __launch_bounds__(256) void gatenorm_kernel(const float* __restrict__ nw)
{
    int row = blockIdx.x;
    int tid = threadIdx.x;
    const float* yr = g_y + (size_t)row * D_INNER;
    const float* zr = g_zx + (size_t)row * D_IN_PROJ;
    float v[8];
    float ss = 0.f;
#pragma unroll
    for (int i = 0; i < 8; i++) {
        int c = tid + i * 256;
        float z = zr[c];
        float val = yr[c] * (z / (1.f + expf(-z)));
        v[i] = val;
        ss = fmaf(val, val, ss);
    }
#pragma unroll
    for (int o = 16; o; o >>= 1) ss += __shfl_xor_sync(0xffffffffu, ss, o);
    __shared__ float red[8];
    if ((tid & 31) == 0) red[tid >> 5] = ss;
    __syncthreads();
    float tot = red[0] + red[1] + red[2] + red[3] + red[4] + red[5] + red[6] + red[7];
    float scale = rsqrtf(tot * (1.0f / 2048.0f) + 1e-5f);
#pragma unroll
    for (int i = 0; i < 8; i++) {
        int c = tid + i * 256;
        float val = v[i] * scale * nw[c];
        __nv_bfloat16 h = __float2bfloat16_rn(val);
        g_nh[(size_t)row * D_INNER + c] = h;
        g_nl[(size_t)row * D_INNER + c] = __float2bfloat16_rn(val - __bfloat162float(h));
    }
}

// =====================================================================
extern "C" void kernel_launch(void* const* d_in, const int* in_sizes, int n_in,
                              void* d_out, int out_size)
{
    const float* x          = (const float*)d_in[0];
    const float* in_proj_w  = (const float*)d_in[1];
    const float* conv_w     = (const float*)d_in[2];
    const float* conv_b     = (const float*)d_in[3];
    const float* dt_bias    = (const float*)d_in[4];
    const float* A_log      = (const float*)d_in[5];
    const float* Dv         = (const float*)d_in[6];
    const float* norm_w     = (const float*)d_in[7];
    const float* out_proj_w = (const float*)d_in[8];
    float* out = (float*)d_out;

    float *zx;
    __nv_bfloat16 *xh, *xl, *w1h, *w1l, *w2h, *w2l, *nh, *nl;
    cudaGetSymbolAddress((void**)&zx, g_zx);
    cudaGetSymbolAddress((void**)&xh, g_xhb);
    cudaGetSymbolAddress((void**)&xl, g_xlb);
    cudaGetSymbolAddress((void**)&w1h, g_w1h);
    cudaGetSymbolAddress((void**)&w1l, g_w1l);
    cudaGetSymbolAddress((void**)&w2h, g_w2h);
    cudaGetSymbolAddress((void**)&w2l, g_w2l);
    cudaGetSymbolAddress((void**)&nh, g_nh);
    cudaGetSymbolAddress((void**)&nl, g_nl);

    cudaFuncSetAttribute(gemm_mma, cudaFuncAttributeMaxDynamicSharedMemorySize, GSMEM);
    cudaFuncSetAttribute(correct_mma_kernel, cudaFuncAttributeMaxDynamicSharedMemorySize, CR_SMEM);

    const int SPLIT_TOT = SPLIT_N0 + SPLIT_N1 + SPLIT_N2;
    split_all_kernel<<<(SPLIT_TOT + 255) / 256, 256>>>(x, in_proj_w, out_proj_w);

    gemm_mma<<<dim3((D_IN_PROJ + 127) / 128, BL / 128), 256, GSMEM>>>(
        xh, xl, w1h, w1l, zx, nullptr, BL, D_IN_PROJ, D_MODEL);

    conv_silu_kernel<<<dim3(10, BL / CT), 256>>>(conv_w, conv_b, dt_bias, A_log);

    scan_local_kernel<<<BATCH * NHEADS * NCHUNK, 128>>>(Dv);
    combine_kernel<<<BATCH * NHEADS * 2, 256>>>();
    correct_mma_kernel<<<BATCH * NHEADS * (NCHUNK - 1), 128, CR_SMEM>>>();

    gatenorm_kernel<<<BL, 256>>>(norm_w);

    gemm_mma<<<dim3(D_MODEL / 128, BL / 128), 256, GSMEM>>>(
        nh, nl, w2h, w2l, out, x, BL, D_MODEL, D_INNER);
}